// round 14
// baseline (speedup 1.0000x reference)
#include <cuda_runtime.h>
#include <math.h>
#include <stdint.h>
#include <string.h>

// ---------------- problem constants ----------------
#define BB 64
#define TT 256
#define LL 16
#define VC 100
#define DC 50
#define CHN 100
#define DW 300
#define DF 20
#define HH 256
#define IND 420          // DW + CHN + DF
#define NT 52            // LAB + 2
#define TSTART 50
#define TSTOP 51

// LSTM partitioning: 4 batch groups x 16 blocks, 16 units/block
#define GRP 4
#define BPG 16           // blocks per (dir,group) barrier domain
#define UPB 16           // units per block
#define SPG 16           // samples per group
#define WSTRIDE 258      // ull stride per (gate,unit) weight row (bank padding)

#define NLSTM 128        // lstm blocks (bids 0..127)
#define NGEMM 256        // gemm blocks (bids 128..383)

typedef unsigned long long ull;

// ---------------- scratch (device globals; no allocations) ----------------
__device__ float d_tbl[3][VC][CHN];                 // conv lookup table
__device__ float d_x[(size_t)TT * BB * IND];        // x, row = t*BB + b
__device__ float d_xs[2][TT][4 * HH][BB];           // input proj, transposed [t][n][b]
__device__ float d_hseq[2][TT][HH][BB];             // per-step hidden states
__device__ float d_feats[(size_t)TT * BB * NT];     // emissions [t][b][n]
__device__ float d_lossp[BB];
__device__ unsigned d_flag[2][GRP * BPG];           // per-block monotonic step flags
__device__ int d_gdone[2][128];                     // gemm m-tile done counters

// ---------------- helpers ----------------
__device__ __forceinline__ void cp16(uint32_t dst_smem, const void* src) {
    asm volatile("cp.async.cg.shared.global [%0], [%1], 16;\n"
                 :: "r"(dst_smem), "l"(src));
}
__device__ __forceinline__ void cp_commit() {
    asm volatile("cp.async.commit_group;\n");
}
template <int N>
__device__ __forceinline__ void cp_wait() {
    asm volatile("cp.async.wait_group %0;\n" :: "n"(N));
}
// packed dual fp32 fma: per-lane IEEE fp32, same rounding as scalar fmaf
__device__ __forceinline__ ull fma2(ull h, ull w, ull acc) {
    ull d;
    asm("fma.rn.f32x2 %0, %1, %2, %3;" : "=l"(d) : "l"(h), "l"(w), "l"(acc));
    return d;
}

// ---------------- 0. zero gemm done counters ----------------
__global__ void k_zero() {
    int i = threadIdx.x;
    ((int*)d_gdone)[i] = 0;
}

// ---------------- 1. conv -> lookup table ----------------
__global__ void k_table(const float* __restrict__ conv_w,
                        const float* __restrict__ char_emb) {
    int idx = blockIdx.x * blockDim.x + threadIdx.x;
    if (idx >= 3 * VC * CHN) return;
    int ch = idx % CHN;
    int c  = (idx / CHN) % VC;
    int kk = idx / (CHN * VC);
    float s = 0.f;
    #pragma unroll 10
    for (int dc = 0; dc < DC; dc++)
        s += conv_w[(ch * DC + dc) * 3 + kk] * char_emb[c * DC + dc];
    d_tbl[kk][c][ch] = s;
}

// ---------------- 2. build x = [word_emb | char_cnn | feat_emb] ----------------
__global__ void k_build_x(const int* __restrict__ word,
                          const int* __restrict__ featidx,
                          const int* __restrict__ chars,
                          const int* __restrict__ recover,
                          const float* __restrict__ word_emb,
                          const float* __restrict__ feat_emb,
                          const float* __restrict__ conv_b) {
    int m = blockIdx.x;           // row = t*BB + b
    int t = m / BB, b = m % BB;
    int tid = threadIdx.x;
    __shared__ int cs[LL];
    float* xr = &d_x[(size_t)m * IND];
    int w = word[b * TT + t];
    const float4* we4 = (const float4*)(word_emb + (size_t)w * DW);
    float4* xr4 = (float4*)xr;
    for (int i = tid; i < DW / 4; i += blockDim.x) xr4[i] = we4[i];
    if (tid < DF) {
        int fv = featidx[b];
        xr[DW + CHN + tid] = feat_emb[fv * DF + tid];
    }
    if (tid < LL) {
        int j = recover[b * TT + t];
        cs[tid] = chars[j * LL + tid];
    }
    __syncthreads();
    if (tid < CHN) {
        float bias = conv_b[tid];
        float mx = -3.4e38f;
        #pragma unroll
        for (int l = 0; l < LL; l++) {
            float v = bias + d_tbl[1][cs[l]][tid];
            if (l > 0)       v += d_tbl[0][cs[l - 1]][tid];
            if (l < LL - 1)  v += d_tbl[2][cs[l + 1]][tid];
            mx = fmaxf(mx, v);
        }
        xr[DW + tid] = mx;
    }
}

// ---------------- 3+4. FUSED gemm + persistent LSTM (single kernel) ----------------
// blocks 0..127  : LSTM (2 dirs x 4 groups x 16 blocks), 128 compute threads +
//                  128 helper threads (sync/stage only). Gated per 2 steps on
//                  d_gdone published by gemm blocks IN THE SAME KERNEL.
// blocks 128..383: GEMM producers; each computes 8 (dir,mt,nt) tiles, striped so
//                  dir0 mts ascend and dir1 mts descend (both LSTM dirs unblock
//                  immediately). Deadlock-free: gemm blocks depend on nothing.
__global__ void __launch_bounds__(256, 2) k_fused(const float* __restrict__ whh_f,
                                                  const float* __restrict__ whh_b,
                                                  const int* __restrict__ lens,
                                                  const float* __restrict__ w_f,
                                                  const float* __restrict__ b_fp,
                                                  const float* __restrict__ w_b,
                                                  const float* __restrict__ b_bp) {
    extern __shared__ float sm[];
    int tid = threadIdx.x;

    if (blockIdx.x >= NLSTM) {
        // ================= GEMM producer path =================
        float* As = sm;                 // [2][16][128]
        float* Bs = sm + 4096;          // [2][16][128]
        int gb  = blockIdx.x - NLSTM;   // 0..255
        int nt  = gb & 7;
        int dir = (gb >> 3) & 1;
        int grp = gb >> 4;              // 0..15
        const float* W    = dir ? w_b  : w_f;
        const float* bias = dir ? b_bp : b_fp;
        int n0 = nt * 128;
        int bq = tid & 15;
        int nq = tid >> 4;
        int r0 = tid >> 2,         kq0 = (tid & 3) << 2;
        int r1 = (tid + 256) >> 2, kq1 = ((tid + 256) & 3) << 2;
        float4 z4 = make_float4(0.f, 0.f, 0.f, 0.f);
        const int KT = 27;

        for (int jt = 0; jt < 8; jt++) {
            int m_lin = jt * 16 + grp;                  // 0..127
            int mt = dir ? (127 - m_lin) : m_lin;       // asc for fwd, desc for bwd
            int m0 = mt * 128;
            const float* A0 = &d_x[(size_t)(m0 + r0) * IND];
            const float* A1 = &d_x[(size_t)(m0 + r1) * IND];
            const float* B0 = &W[(size_t)(n0 + r0) * IND];
            const float* B1 = &W[(size_t)(n0 + r1) * IND];

            float acc[8][8];
            #pragma unroll
            for (int i = 0; i < 8; i++)
                #pragma unroll
                for (int j = 0; j < 8; j++) acc[i][j] = 0.f;

            float4 ra0, ra1, rb0, rb1;
            {
                ra0 = (kq0 < IND) ? *(const float4*)(A0 + kq0) : z4;
                ra1 = (kq1 < IND) ? *(const float4*)(A1 + kq1) : z4;
                rb0 = (kq0 < IND) ? *(const float4*)(B0 + kq0) : z4;
                rb1 = (kq1 < IND) ? *(const float4*)(B1 + kq1) : z4;
                As[(kq0 + 0) * 128 + r0] = ra0.x; As[(kq0 + 1) * 128 + r0] = ra0.y;
                As[(kq0 + 2) * 128 + r0] = ra0.z; As[(kq0 + 3) * 128 + r0] = ra0.w;
                As[(kq1 + 0) * 128 + r1] = ra1.x; As[(kq1 + 1) * 128 + r1] = ra1.y;
                As[(kq1 + 2) * 128 + r1] = ra1.z; As[(kq1 + 3) * 128 + r1] = ra1.w;
                Bs[(kq0 + 0) * 128 + r0] = rb0.x; Bs[(kq0 + 1) * 128 + r0] = rb0.y;
                Bs[(kq0 + 2) * 128 + r0] = rb0.z; Bs[(kq0 + 3) * 128 + r0] = rb0.w;
                Bs[(kq1 + 0) * 128 + r1] = rb1.x; Bs[(kq1 + 1) * 128 + r1] = rb1.y;
                Bs[(kq1 + 2) * 128 + r1] = rb1.z; Bs[(kq1 + 3) * 128 + r1] = rb1.w;
            }
            __syncthreads();

            int buf = 0;
            for (int kt = 0; kt < KT; kt++) {
                if (kt + 1 < KT) {
                    int k0 = (kt + 1) * 16;
                    ra0 = (k0 + kq0 < IND) ? *(const float4*)(A0 + k0 + kq0) : z4;
                    ra1 = (k0 + kq1 < IND) ? *(const float4*)(A1 + k0 + kq1) : z4;
                    rb0 = (k0 + kq0 < IND) ? *(const float4*)(B0 + k0 + kq0) : z4;
                    rb1 = (k0 + kq1 < IND) ? *(const float4*)(B1 + k0 + kq1) : z4;
                }
                float* Ab = As + buf * 2048;
                float* Bb = Bs + buf * 2048;
                #pragma unroll
                for (int k = 0; k < 16; k++) {
                    float4 a0 = *(const float4*)&Ab[k * 128 + bq * 8];
                    float4 a1 = *(const float4*)&Ab[k * 128 + bq * 8 + 4];
                    float4 bv0 = *(const float4*)&Bb[k * 128 + nq * 8];
                    float4 bv1 = *(const float4*)&Bb[k * 128 + nq * 8 + 4];
                    float am[8] = {a0.x, a0.y, a0.z, a0.w, a1.x, a1.y, a1.z, a1.w};
                    float bn[8] = {bv0.x, bv0.y, bv0.z, bv0.w,
                                   bv1.x, bv1.y, bv1.z, bv1.w};
                    #pragma unroll
                    for (int i = 0; i < 8; i++)
                        #pragma unroll
                        for (int j = 0; j < 8; j++)
                            acc[i][j] += am[i] * bn[j];
                }
                if (kt + 1 < KT) {
                    int nb = buf ^ 1;
                    float* An = As + nb * 2048;
                    float* Bn = Bs + nb * 2048;
                    An[(kq0 + 0) * 128 + r0] = ra0.x; An[(kq0 + 1) * 128 + r0] = ra0.y;
                    An[(kq0 + 2) * 128 + r0] = ra0.z; An[(kq0 + 3) * 128 + r0] = ra0.w;
                    An[(kq1 + 0) * 128 + r1] = ra1.x; An[(kq1 + 1) * 128 + r1] = ra1.y;
                    An[(kq1 + 2) * 128 + r1] = ra1.z; An[(kq1 + 3) * 128 + r1] = ra1.w;
                    Bn[(kq0 + 0) * 128 + r0] = rb0.x; Bn[(kq0 + 1) * 128 + r0] = rb0.y;
                    Bn[(kq0 + 2) * 128 + r0] = rb0.z; Bn[(kq0 + 3) * 128 + r0] = rb0.w;
                    Bn[(kq1 + 0) * 128 + r1] = rb1.x; Bn[(kq1 + 1) * 128 + r1] = rb1.y;
                    Bn[(kq1 + 2) * 128 + r1] = rb1.z; Bn[(kq1 + 3) * 128 + r1] = rb1.w;
                    __syncthreads();
                    buf = nb;
                }
            }

            float* out = &d_xs[dir][0][0][0];
            #pragma unroll
            for (int j = 0; j < 8; j++) {
                int n = n0 + nq * 8 + j;
                float bz = bias[n];
                #pragma unroll
                for (int i4 = 0; i4 < 8; i4 += 4) {
                    int m = m0 + bq * 8 + i4;
                    int t = m >> 6, bb = m & 63;
                    float4 o;
                    o.x = acc[i4 + 0][j] + bz; o.y = acc[i4 + 1][j] + bz;
                    o.z = acc[i4 + 2][j] + bz; o.w = acc[i4 + 3][j] + bz;
                    *(float4*)&out[((size_t)t * 1024 + n) * 64 + bb] = o;
                }
            }
            // publish tile (release) — also guards smem reuse for next tile
            __threadfence();
            __syncthreads();
            if (tid == 0) atomicAdd(&d_gdone[dir][mt], 1);
            __syncthreads();
        }
        return;
    }

    // ================= LSTM path (blocks 0..127) =================
    float* Ws2f = sm;                       // 64 rows x WSTRIDE ull (dup pairs) 132KB
    float* hsm  = sm + 2 * 64 * WSTRIDE;    // 16 samples x 256 units, 16KB
    int blk = blockIdx.x;
    int dir = blk >> 6;
    int g   = (blk >> 4) & 3;
    int lb  = blk & 15;
    int ub  = lb * UPB;
    int uj  = tid >> 3;              // unit 0..15 (valid for tid<128)
    int bp  = tid & 7;               // sample pair 0..7
    int sb  = g * SPG + 2 * bp;      // global sample index (even)
    const float* whh = dir ? whh_b : whh_f;

    // load W (dup pairs), rows r = gate*16 + ju  (all 256 threads)
    for (int i = tid; i < 4 * UPB * HH; i += 256) {
        int k = i & (HH - 1);
        int r = i >> 8;
        int gate = r >> 4, ju = r & 15;
        float w = whh[(size_t)(gate * HH + ub + ju) * HH + k];
        Ws2f[2 * (r * WSTRIDE + k)]     = w;
        Ws2f[2 * (r * WSTRIDE + k) + 1] = w;
    }
    int len0 = lens[sb];
    int len1 = lens[sb + 1];
    int u = ub + uj;
    float c0 = 0.f, h0v = 0.f, c1 = 0.f, h1v = 0.f;
    volatile unsigned* flags = (volatile unsigned*)&d_flag[dir][g * BPG];
    unsigned gen0 = flags[lb];
    const float* xs_base = &d_xs[dir][0][0][0];
    float* hq_base = &d_hseq[dir][0][0][0];
    uint32_t hsm_s = (uint32_t)__cvta_generic_to_shared(hsm);
    const ull* W2 = (const ull*)Ws2f;
    int mt_done = -1;
    __syncthreads();

    for (int s = 0; s < TT; s++) {
        int t = dir ? (TT - 1 - s) : s;
        // ---- wait for this t's gemm tile (once per 2 steps) ----
        int mt = t >> 1;
        if (mt != mt_done) {
            if (tid == 0) {
                while (*(volatile int*)&d_gdone[dir][mt] < 8) __nanosleep(64);
            }
            __syncthreads();
            __threadfence();   // acquire for xs reads
            mt_done = mt;
        }
        const float* xsp = xs_base + (size_t)t * 1024 * 64;
        float2 x0, x1, x2, x3;
        if (tid < 128) {
            x0 = *(const float2*)(xsp + (0 * HH + u) * 64 + sb);
            x1 = *(const float2*)(xsp + (1 * HH + u) * 64 + sb);
            x2 = *(const float2*)(xsp + (2 * HH + u) * 64 + sb);
            x3 = *(const float2*)(xsp + (3 * HH + u) * 64 + sb);
        }
        ull a0 = 0ull, a1 = 0ull, a2 = 0ull, a3 = 0ull;
        if (s > 0) {
            // per-thread spin on the 16 domain flags
            unsigned target = gen0 + (unsigned)s;
            if (tid < BPG) {
                while (flags[tid] < target) { __nanosleep(32); }
            }
            __syncthreads();
            __threadfence();
            // stage h slab (16KB) in 4 chunks of 4KB; 256 threads -> 1 cp each
            int tp = dir ? (t + 1) : (t - 1);
            const float* hsrc = hq_base + (size_t)tp * HH * BB;
            #pragma unroll
            for (int cc = 0; cc < 4; cc++) {
                int r = tid >> 2, c = tid & 3;        // unit-within-chunk, 16B col
                cp16(hsm_s + (uint32_t)(cc * 4096 + r * 64 + c * 16),
                     hsrc + (size_t)(cc * 64 + r) * 64 + g * SPG + c * 4);
                cp_commit();
            }
            const ull* H2 = (const ull*)hsm;
            // chunk-overlapped compute; fma2 order identical to R10 (bit-exact)
            #pragma unroll
            for (int c4 = 0; c4 < 4; c4++) {
                if (c4 == 0) cp_wait<3>();
                else if (c4 == 1) cp_wait<2>();
                else if (c4 == 2) cp_wait<1>();
                else cp_wait<0>();
                __syncthreads();
                if (tid < 128) {
                    const ull* w0 = W2 + (0 * UPB + uj) * WSTRIDE + c4 * 64;
                    const ull* w1 = W2 + (1 * UPB + uj) * WSTRIDE + c4 * 64;
                    const ull* w2 = W2 + (2 * UPB + uj) * WSTRIDE + c4 * 64;
                    const ull* w3 = W2 + (3 * UPB + uj) * WSTRIDE + c4 * 64;
                    const ull* hc = H2 + c4 * 64 * 8;
                    #pragma unroll
                    for (int kk = 0; kk < 64; kk += 8) {
                        ull hr[8];
                        #pragma unroll
                        for (int i = 0; i < 8; i++)
                            hr[i] = hc[(kk + i) * 8 + bp];
                        #pragma unroll
                        for (int i = 0; i < 8; i += 2) {
                            ulonglong2 q0 = *(const ulonglong2*)(w0 + kk + i);
                            ulonglong2 q1 = *(const ulonglong2*)(w1 + kk + i);
                            ulonglong2 q2 = *(const ulonglong2*)(w2 + kk + i);
                            ulonglong2 q3 = *(const ulonglong2*)(w3 + kk + i);
                            a0 = fma2(hr[i], q0.x, a0); a0 = fma2(hr[i + 1], q0.y, a0);
                            a1 = fma2(hr[i], q1.x, a1); a1 = fma2(hr[i + 1], q1.y, a1);
                            a2 = fma2(hr[i], q2.x, a2); a2 = fma2(hr[i + 1], q2.y, a2);
                            a3 = fma2(hr[i], q3.x, a3); a3 = fma2(hr[i + 1], q3.y, a3);
                        }
                    }
                }
            }
        }
        if (tid < 128) {
            float2 av0, av1, av2, av3;
            memcpy(&av0, &a0, 8); memcpy(&av1, &a1, 8);
            memcpy(&av2, &a2, 8); memcpy(&av3, &a3, 8);
            // sample 0
            {
                float g0 = x0.x + av0.x, g1 = x1.x + av1.x;
                float g2 = x2.x + av2.x, g3 = x3.x + av3.x;
                float ig = 1.f / (1.f + expf(-g0));
                float fg = 1.f / (1.f + expf(-g1));
                float gg = tanhf(g2);
                float og = 1.f / (1.f + expf(-g3));
                float cn = fg * c0 + ig * gg;
                float hn = og * tanhf(cn);
                if (t < len0) { c0 = cn; h0v = hn; }
            }
            // sample 1
            {
                float g0 = x0.y + av0.y, g1 = x1.y + av1.y;
                float g2 = x2.y + av2.y, g3 = x3.y + av3.y;
                float ig = 1.f / (1.f + expf(-g0));
                float fg = 1.f / (1.f + expf(-g1));
                float gg = tanhf(g2);
                float og = 1.f / (1.f + expf(-g3));
                float cn = fg * c1 + ig * gg;
                float hn = og * tanhf(cn);
                if (t < len1) { c1 = cn; h1v = hn; }
            }
            float2 hw; hw.x = h0v; hw.y = h1v;
            *(float2*)(hq_base + ((size_t)t * HH + u) * BB + sb) = hw;
        }
        // publish (release: every thread fences, then flag bump)
        __threadfence();
        __syncthreads();
        if (tid == 0) {
            atomicExch((unsigned*)&d_flag[dir][g * BPG + lb],
                       gen0 + (unsigned)s + 1u);
        }
    }
}

// ---------------- 5. projection + mask -> feats[t][b][n] ----------------
__global__ void __launch_bounds__(256) k_proj(const float* __restrict__ proj_w,
                                              const float* __restrict__ proj_b,
                                              const int* __restrict__ lens) {
    __shared__ float hsm[64][64];
    __shared__ float pw[NT][64];
    int t = blockIdx.x;
    int tid = threadIdx.x;
    int b = tid & 63, grp = tid >> 6;
    float acc[13];
    #pragma unroll
    for (int r = 0; r < 13; r++) acc[r] = 0.f;

    for (int kc = 0; kc < 8; kc++) {
        int u512 = kc * 64;
        int dir = u512 >> 8;
        int ubo = u512 & 255;
        const float* hp = &d_hseq[dir][t][ubo][0];
        #pragma unroll
        for (int i = 0; i < 16; i++) {
            int idx = tid + i * 256;
            hsm[idx >> 6][idx & 63] = hp[idx];
        }
        for (int i = tid; i < NT * 64; i += 256) {
            int n = i >> 6, k = i & 63;
            pw[n][k] = proj_w[(size_t)n * (2 * HH) + kc * 64 + k];
        }
        __syncthreads();
        for (int k = 0; k < 64; k++) {
            float hv = hsm[k][b];
            #pragma unroll
            for (int r = 0; r < 13; r++)
                acc[r] += hv * pw[grp * 13 + r][k];
        }
        __syncthreads();
    }
    int msk = (t < lens[b]) ? 1 : 0;
    #pragma unroll
    for (int r = 0; r < 13; r++) {
        int n = grp * 13 + r;
        d_feats[((size_t)t * 64 + b) * NT + n] = (msk ? acc[r] : 0.f) + proj_b[n];
    }
}

// ---------------- 6. CRF: forward Z + viterbi + gold + tags ----------------
__global__ void __launch_bounds__(64) k_crf(const float* __restrict__ transitions,
                                            const int* __restrict__ lens,
                                            const int* __restrict__ labels,
                                            float* __restrict__ out) {
    __shared__ float tr[NT * NT];
    __shared__ float E[NT * NT];
    __shared__ float alpha[2][64], vv[2][64], ea[64], red[64];
    __shared__ unsigned char bps[TT][NT];
    __shared__ int s_best_last;
    int b = blockIdx.x;
    int j = threadIdx.x;

    for (int i = j; i < NT * NT; i += 64) {
        float x = transitions[i];
        tr[i] = x;
        E[i] = expf(x);
    }
    __syncthreads();
    int len = lens[b];

    float aj = -INFINITY;
    if (j < NT) aj = d_feats[(size_t)(0 * 64 + b) * NT + j] + tr[TSTART * NT + j];
    alpha[0][j] = aj;
    vv[0][j] = aj;
    __syncthreads();

    int p = 0;
    for (int t = 1; t < len; t++) {
        int q = p ^ 1;
        float m = alpha[p][0];
        ea[j] = (j < NT) ? expf(alpha[p][j] - m) : 0.f;
        __syncthreads();
        if (j < NT) {
            float ff = d_feats[((size_t)t * 64 + b) * NT + j];
            float s = 0.f;
            #pragma unroll 4
            for (int i = 0; i < NT; i++) s += ea[i] * E[i * NT + j];
            float best = -INFINITY; int bp = 0;
            for (int i = 0; i < NT; i++) {
                float sij = ff + tr[i * NT + j];
                float cnd = vv[p][i] + sij;
                if (cnd > best) { best = cnd; bp = i; }
            }
            alpha[q][j] = m + logf(s) + ff;
            vv[q][j] = best;
            bps[t][j] = (unsigned char)bp;
        }
        __syncthreads();
        p = q;
    }

    float zx = (j < NT) ? alpha[p][j] + tr[j * NT + TSTOP] : -INFINITY;
    red[j] = zx;
    __syncthreads();
    for (int off = 32; off >= 1; off >>= 1) {
        if (j < off) red[j] = fmaxf(red[j], red[j + off]);
        __syncthreads();
    }
    float zm = red[0];
    __syncthreads();
    red[j] = (j < NT) ? expf(zx - zm) : 0.f;
    __syncthreads();
    for (int off = 32; off >= 1; off >>= 1) {
        if (j < off) red[j] += red[j + off];
        __syncthreads();
    }
    float Z = zm + logf(red[0]);
    __syncthreads();

    red[j] = (j < NT) ? vv[p][j] + tr[j * NT + TSTOP] : -INFINITY;
    __syncthreads();
    if (j == 0) {
        float bv = -INFINITY; int bi = 0;
        for (int i = 0; i < NT; i++)
            if (red[i] > bv) { bv = red[i]; bi = i; }
        s_best_last = bi;
    }
    __syncthreads();
    int best_last = s_best_last;
    __syncthreads();

    float gp = 0.f;
    for (int t = j; t < TT; t += 64) {
        if (t < len) {
            int lab = labels[b * TT + t];
            gp += d_feats[((size_t)t * 64 + b) * NT + lab];
            if (t >= 1) gp += tr[labels[b * TT + t - 1] * NT + lab];
        }
    }
    red[j] = gp;
    __syncthreads();
    for (int off = 32; off >= 1; off >>= 1) {
        if (j < off) red[j] += red[j + off];
        __syncthreads();
    }
    if (j == 0) {
        int l0 = labels[b * TT + 0];
        int ll = labels[b * TT + len - 1];
        float gold = red[0] + tr[TSTART * NT + l0] + tr[ll * NT + TSTOP];
        d_lossp[b] = Z - gold;
    }

    if (j == 0) {
        int cur = best_last;
        for (int t = TT - 1; t >= 0; --t) {
            out[1 + b * TT + t] = (t < len) ? (float)cur : 0.f;
            if (t > 0 && t < len) cur = (int)bps[t][cur];
        }
    }
}

// ---------------- 7. loss reduction ----------------
__global__ void k_loss(float* __restrict__ out) {
    __shared__ float red[64];
    int j = threadIdx.x;
    red[j] = d_lossp[j];
    __syncthreads();
    for (int off = 32; off >= 1; off >>= 1) {
        if (j < off) red[j] += red[j + off];
        __syncthreads();
    }
    if (j == 0) out[0] = red[0];
}

// ---------------- launch ----------------
extern "C" void kernel_launch(void* const* d_in, const int* in_sizes, int n_in,
                              void* d_out, int out_size) {
    const int*   batch_word     = (const int*)  d_in[0];
    const int*   batch_features = (const int*)  d_in[1];
    const int*   batch_wordlen  = (const int*)  d_in[2];
    const int*   batch_char     = (const int*)  d_in[3];
    const int*   charrecover    = (const int*)  d_in[5];
    const int*   batch_label    = (const int*)  d_in[7];
    const float* char_emb       = (const float*)d_in[8];
    const float* conv_w         = (const float*)d_in[9];
    const float* conv_b         = (const float*)d_in[10];
    const float* word_emb       = (const float*)d_in[11];
    const float* feat_emb       = (const float*)d_in[12];
    const float* w_ih_f         = (const float*)d_in[13];
    const float* w_hh_f         = (const float*)d_in[14];
    const float* b_f            = (const float*)d_in[15];
    const float* w_ih_b         = (const float*)d_in[16];
    const float* w_hh_b         = (const float*)d_in[17];
    const float* b_b            = (const float*)d_in[18];
    const float* proj_w         = (const float*)d_in[19];
    const float* proj_b         = (const float*)d_in[20];
    const float* transitions    = (const float*)d_in[21];
    float* out = (float*)d_out;
    (void)in_sizes; (void)n_in; (void)out_size;

    const int fused_smem = (2 * 64 * WSTRIDE + 4096) * (int)sizeof(float);
    static int init_done = 0;
    if (!init_done) {
        cudaFuncSetAttribute(k_fused, cudaFuncAttributeMaxDynamicSharedMemorySize,
                             fused_smem);
        init_done = 1;
    }

    k_zero<<<1, 256>>>();
    k_table<<<(3 * VC * CHN + 255) / 256, 256>>>(conv_w, char_emb);
    k_build_x<<<TT * BB, 128>>>(batch_word, batch_features, batch_char,
                                charrecover, word_emb, feat_emb, conv_b);
    k_fused<<<NLSTM + NGEMM, 256, fused_smem>>>(w_hh_f, w_hh_b, batch_wordlen,
                                                w_ih_f, b_f, w_ih_b, b_b);
    k_proj<<<TT, 256>>>(proj_w, proj_b, batch_wordlen);
    k_crf<<<BB, 64>>>(transitions, batch_wordlen, batch_label, out);
    k_loss<<<1, 64>>>(out);
}

// round 16
// speedup vs baseline: 3.1175x; 3.1175x over previous
#include <cuda_runtime.h>
#include <math.h>
#include <stdint.h>
#include <string.h>

// ---------------- problem constants ----------------
#define BB 64
#define TT 256
#define LL 16
#define VC 100
#define DC 50
#define CHN 100
#define DW 300
#define DF 20
#define HH 256
#define IND 420          // DW + CHN + DF
#define NT 52            // LAB + 2
#define TSTART 50
#define TSTOP 51

// LSTM partitioning: 4 batch groups x 16 blocks, 16 units/block
#define GRP 4
#define BPG 16           // blocks per (dir,group) barrier domain
#define UPB 16           // units per block
#define SPG 16           // samples per group
#define WS_F 264         // float stride per (gate,unit) weight row (bank padding)

#define NLSTM 128        // lstm blocks (bids 0..127)
#define NG    160        // gemm blocks (bids 128..287)

typedef unsigned long long ull;

// ---------------- scratch (device globals; no allocations) ----------------
__device__ float d_tbl[3][VC][CHN];                 // conv lookup table
__device__ float d_x[(size_t)TT * BB * IND];        // x, row = t*BB + b
__device__ float d_xs[2][TT][4 * HH][BB];           // input proj, transposed [t][n][b]
__device__ float d_hseq[2][TT][HH][BB];             // per-step hidden states
__device__ float d_feats[(size_t)TT * BB * NT];     // emissions [t][b][n]
__device__ float d_lossp[BB];
__device__ unsigned d_flag[2][GRP * BPG];           // per-block monotonic step flags
__device__ int d_gdone[2][128];                     // gemm m-tile done counters

// ---------------- helpers ----------------
__device__ __forceinline__ void cp16(uint32_t dst_smem, const void* src) {
    asm volatile("cp.async.cg.shared.global [%0], [%1], 16;\n"
                 :: "r"(dst_smem), "l"(src));
}
__device__ __forceinline__ void cp_commit() {
    asm volatile("cp.async.commit_group;\n");
}
template <int N>
__device__ __forceinline__ void cp_wait() {
    asm volatile("cp.async.wait_group %0;\n" :: "n"(N));
}

// ---------------- 0. zero gemm done counters ----------------
__global__ void k_zero() {
    int i = threadIdx.x;
    ((int*)d_gdone)[i] = 0;
}

// ---------------- 1. conv -> lookup table ----------------
__global__ void k_table(const float* __restrict__ conv_w,
                        const float* __restrict__ char_emb) {
    int idx = blockIdx.x * blockDim.x + threadIdx.x;
    if (idx >= 3 * VC * CHN) return;
    int ch = idx % CHN;
    int c  = (idx / CHN) % VC;
    int kk = idx / (CHN * VC);
    float s = 0.f;
    #pragma unroll 10
    for (int dc = 0; dc < DC; dc++)
        s += conv_w[(ch * DC + dc) * 3 + kk] * char_emb[c * DC + dc];
    d_tbl[kk][c][ch] = s;
}

// ---------------- 2. build x = [word_emb | char_cnn | feat_emb] ----------------
__global__ void k_build_x(const int* __restrict__ word,
                          const int* __restrict__ featidx,
                          const int* __restrict__ chars,
                          const int* __restrict__ recover,
                          const float* __restrict__ word_emb,
                          const float* __restrict__ feat_emb,
                          const float* __restrict__ conv_b) {
    int m = blockIdx.x;           // row = t*BB + b
    int t = m / BB, b = m % BB;
    int tid = threadIdx.x;
    __shared__ int cs[LL];
    float* xr = &d_x[(size_t)m * IND];
    int w = word[b * TT + t];
    const float4* we4 = (const float4*)(word_emb + (size_t)w * DW);
    float4* xr4 = (float4*)xr;
    for (int i = tid; i < DW / 4; i += blockDim.x) xr4[i] = we4[i];
    if (tid < DF) {
        int fv = featidx[b];
        xr[DW + CHN + tid] = feat_emb[fv * DF + tid];
    }
    if (tid < LL) {
        int j = recover[b * TT + t];
        cs[tid] = chars[j * LL + tid];
    }
    __syncthreads();
    if (tid < CHN) {
        float bias = conv_b[tid];
        float mx = -3.4e38f;
        #pragma unroll
        for (int l = 0; l < LL; l++) {
            float v = bias + d_tbl[1][cs[l]][tid];
            if (l > 0)       v += d_tbl[0][cs[l - 1]][tid];
            if (l < LL - 1)  v += d_tbl[2][cs[l + 1]][tid];
            mx = fmaxf(mx, v);
        }
        xr[DW + tid] = mx;
    }
}

// ---------------- 3+4. FUSED gemm + persistent LSTM (single kernel, all wave-1) ----
// 288 blocks, 84KB smem each, __launch_bounds__(256,2) => 2 blocks/SM => all 288
// resident in wave 1 (148 SMs x 2 = 296 slots). Even at 1 block/SM the GEMM
// blocks EXIT after their sweep, so producers always progress: deadlock-free.
// blocks 0..127  : LSTM, 256 scalar threads = 16 units x 16 samples.
// blocks 128..287: GEMM producers; block gb sweeps tiles j = gb, gb+160, ...
//                  (j: dir=j&1, nt=(j>>1)&7, mlin=j>>4; mt asc fwd / desc bwd).
__global__ void __launch_bounds__(256, 2) k_fused(const float* __restrict__ whh_f,
                                                  const float* __restrict__ whh_b,
                                                  const int* __restrict__ lens,
                                                  const float* __restrict__ w_f,
                                                  const float* __restrict__ b_fp,
                                                  const float* __restrict__ w_b,
                                                  const float* __restrict__ b_bp) {
    extern __shared__ float sm[];
    int tid = threadIdx.x;

    if (blockIdx.x >= NLSTM) {
        // ================= GEMM producer path (uses 32KB of smem) =================
        float* As = sm;                 // [2][16][128]
        float* Bs = sm + 4096;
        int gb  = blockIdx.x - NLSTM;   // 0..159
        int bq = tid & 15;
        int nq = tid >> 4;
        int r0 = tid >> 2,         kq0 = (tid & 3) << 2;
        int r1 = (tid + 256) >> 2, kq1 = ((tid + 256) & 3) << 2;
        float4 z4 = make_float4(0.f, 0.f, 0.f, 0.f);
        const int KT = 27;

        for (int j = gb; j < 2048; j += NG) {
            int dir  = j & 1;
            int nt   = (j >> 1) & 7;
            int mlin = j >> 4;
            int mt   = dir ? (127 - mlin) : mlin;
            const float* W    = dir ? w_b  : w_f;
            const float* bias = dir ? b_bp : b_fp;
            int m0 = mt * 128;
            int n0 = nt * 128;
            const float* A0 = &d_x[(size_t)(m0 + r0) * IND];
            const float* A1 = &d_x[(size_t)(m0 + r1) * IND];
            const float* B0 = &W[(size_t)(n0 + r0) * IND];
            const float* B1 = &W[(size_t)(n0 + r1) * IND];

            float acc[8][8];
            #pragma unroll
            for (int i = 0; i < 8; i++)
                #pragma unroll
                for (int jj = 0; jj < 8; jj++) acc[i][jj] = 0.f;

            float4 ra0, ra1, rb0, rb1;
            {
                ra0 = (kq0 < IND) ? *(const float4*)(A0 + kq0) : z4;
                ra1 = (kq1 < IND) ? *(const float4*)(A1 + kq1) : z4;
                rb0 = (kq0 < IND) ? *(const float4*)(B0 + kq0) : z4;
                rb1 = (kq1 < IND) ? *(const float4*)(B1 + kq1) : z4;
                As[(kq0 + 0) * 128 + r0] = ra0.x; As[(kq0 + 1) * 128 + r0] = ra0.y;
                As[(kq0 + 2) * 128 + r0] = ra0.z; As[(kq0 + 3) * 128 + r0] = ra0.w;
                As[(kq1 + 0) * 128 + r1] = ra1.x; As[(kq1 + 1) * 128 + r1] = ra1.y;
                As[(kq1 + 2) * 128 + r1] = ra1.z; As[(kq1 + 3) * 128 + r1] = ra1.w;
                Bs[(kq0 + 0) * 128 + r0] = rb0.x; Bs[(kq0 + 1) * 128 + r0] = rb0.y;
                Bs[(kq0 + 2) * 128 + r0] = rb0.z; Bs[(kq0 + 3) * 128 + r0] = rb0.w;
                Bs[(kq1 + 0) * 128 + r1] = rb1.x; Bs[(kq1 + 1) * 128 + r1] = rb1.y;
                Bs[(kq1 + 2) * 128 + r1] = rb1.z; Bs[(kq1 + 3) * 128 + r1] = rb1.w;
            }
            __syncthreads();

            int buf = 0;
            for (int kt = 0; kt < KT; kt++) {
                if (kt + 1 < KT) {
                    int k0 = (kt + 1) * 16;
                    ra0 = (k0 + kq0 < IND) ? *(const float4*)(A0 + k0 + kq0) : z4;
                    ra1 = (k0 + kq1 < IND) ? *(const float4*)(A1 + k0 + kq1) : z4;
                    rb0 = (k0 + kq0 < IND) ? *(const float4*)(B0 + k0 + kq0) : z4;
                    rb1 = (k0 + kq1 < IND) ? *(const float4*)(B1 + k0 + kq1) : z4;
                }
                float* Ab = As + buf * 2048;
                float* Bb = Bs + buf * 2048;
                #pragma unroll
                for (int k = 0; k < 16; k++) {
                    float4 a0 = *(const float4*)&Ab[k * 128 + bq * 8];
                    float4 a1 = *(const float4*)&Ab[k * 128 + bq * 8 + 4];
                    float4 bv0 = *(const float4*)&Bb[k * 128 + nq * 8];
                    float4 bv1 = *(const float4*)&Bb[k * 128 + nq * 8 + 4];
                    float am[8] = {a0.x, a0.y, a0.z, a0.w, a1.x, a1.y, a1.z, a1.w};
                    float bn[8] = {bv0.x, bv0.y, bv0.z, bv0.w,
                                   bv1.x, bv1.y, bv1.z, bv1.w};
                    #pragma unroll
                    for (int i = 0; i < 8; i++)
                        #pragma unroll
                        for (int jj = 0; jj < 8; jj++)
                            acc[i][jj] += am[i] * bn[jj];
                }
                if (kt + 1 < KT) {
                    int nb = buf ^ 1;
                    float* An = As + nb * 2048;
                    float* Bn = Bs + nb * 2048;
                    An[(kq0 + 0) * 128 + r0] = ra0.x; An[(kq0 + 1) * 128 + r0] = ra0.y;
                    An[(kq0 + 2) * 128 + r0] = ra0.z; An[(kq0 + 3) * 128 + r0] = ra0.w;
                    An[(kq1 + 0) * 128 + r1] = ra1.x; An[(kq1 + 1) * 128 + r1] = ra1.y;
                    An[(kq1 + 2) * 128 + r1] = ra1.z; An[(kq1 + 3) * 128 + r1] = ra1.w;
                    Bn[(kq0 + 0) * 128 + r0] = rb0.x; Bn[(kq0 + 1) * 128 + r0] = rb0.y;
                    Bn[(kq0 + 2) * 128 + r0] = rb0.z; Bn[(kq0 + 3) * 128 + r0] = rb0.w;
                    Bn[(kq1 + 0) * 128 + r1] = rb1.x; Bn[(kq1 + 1) * 128 + r1] = rb1.y;
                    Bn[(kq1 + 2) * 128 + r1] = rb1.z; Bn[(kq1 + 3) * 128 + r1] = rb1.w;
                    __syncthreads();
                    buf = nb;
                }
            }

            float* out = &d_xs[dir][0][0][0];
            #pragma unroll
            for (int jj = 0; jj < 8; jj++) {
                int n = n0 + nq * 8 + jj;
                float bz = bias[n];
                #pragma unroll
                for (int i4 = 0; i4 < 8; i4 += 4) {
                    int m = m0 + bq * 8 + i4;
                    int t = m >> 6, bb = m & 63;
                    float4 o;
                    o.x = acc[i4 + 0][jj] + bz; o.y = acc[i4 + 1][jj] + bz;
                    o.z = acc[i4 + 2][jj] + bz; o.w = acc[i4 + 3][jj] + bz;
                    *(float4*)&out[((size_t)t * 1024 + n) * 64 + bb] = o;
                }
            }
            // publish tile (release: all threads fence own stores, then count)
            __threadfence();
            __syncthreads();
            if (tid == 0) atomicAdd(&d_gdone[dir][mt], 1);
            __syncthreads();
        }
        return;
    }

    // ================= LSTM path (blocks 0..127), scalar 16u x 16s =================
    float* Wsf = sm;                    // 64 rows x WS_F floats (67.6KB)
    float* hsm = sm + 64 * WS_F;        // [k 0..255][sp 0..15] (16KB)
    int blk = blockIdx.x;
    int dir = blk >> 6;
    int g   = (blk >> 4) & 3;
    int lb  = blk & 15;
    int ub  = lb * UPB;
    int uj  = tid >> 4;              // unit 0..15
    int sp  = tid & 15;              // sample 0..15
    int sbs = g * SPG + sp;          // global sample
    const float* whh = dir ? whh_b : whh_f;

    // load W (non-dup), rows r = gate*16 + ju
    for (int i = tid; i < 4 * UPB * HH; i += 256) {
        int k = i & (HH - 1);
        int r = i >> 8;
        int gate = r >> 4, ju = r & 15;
        Wsf[r * WS_F + k] = whh[(size_t)(gate * HH + ub + ju) * HH + k];
    }
    int len_b = lens[sbs];
    int u = ub + uj;
    float cst = 0.f, hst = 0.f;
    volatile unsigned* flags = (volatile unsigned*)&d_flag[dir][g * BPG];
    unsigned gen0 = flags[lb];
    const float* xs_base = &d_xs[dir][0][0][0];
    float* hq_base = &d_hseq[dir][0][0][0];
    uint32_t hsm_s = (uint32_t)__cvta_generic_to_shared(hsm);
    int mt_done = -1;
    __syncthreads();

    for (int s = 0; s < TT; s++) {
        int t = dir ? (TT - 1 - s) : s;
        // ---- wait for this t's gemm tile (once per 2 steps) ----
        int mt = t >> 1;
        if (mt != mt_done) {
            if (tid == 0) {
                while (*(volatile int*)&d_gdone[dir][mt] < 8) __nanosleep(64);
            }
            __syncthreads();
            __threadfence();   // acquire for xs reads
            mt_done = mt;
        }
        const float* xsp = xs_base + (size_t)t * 1024 * 64;
        float x0 = xsp[(0 * HH + u) * 64 + sbs];
        float x1 = xsp[(1 * HH + u) * 64 + sbs];
        float x2 = xsp[(2 * HH + u) * 64 + sbs];
        float x3 = xsp[(3 * HH + u) * 64 + sbs];
        float a0 = 0.f, a1 = 0.f, a2 = 0.f, a3 = 0.f;
        if (s > 0) {
            // per-thread spin on the 16 domain flags
            unsigned target = gen0 + (unsigned)s;
            if (tid < BPG) {
                while (flags[tid] < target) { __nanosleep(32); }
            }
            __syncthreads();
            __threadfence();
            // stage h slab (16KB) in 4 chunks of 4KB, 1 cp16/thread/chunk
            int tp = dir ? (t + 1) : (t - 1);
            const float* hsrc = hq_base + (size_t)tp * HH * BB;
            #pragma unroll
            for (int cc = 0; cc < 4; cc++) {
                int r = tid >> 2, c = tid & 3;        // unit-within-chunk, 16B col
                cp16(hsm_s + (uint32_t)(cc * 4096 + r * 64 + c * 16),
                     hsrc + (size_t)(cc * 64 + r) * 64 + g * SPG + c * 4);
                cp_commit();
            }
            // chunk-overlapped compute; per-(unit,sample) fmaf chains with the
            // SAME ascending-k order as the fma2 lanes => bit-exact
            #pragma unroll
            for (int c4 = 0; c4 < 4; c4++) {
                if (c4 == 0) cp_wait<3>();
                else if (c4 == 1) cp_wait<2>();
                else if (c4 == 2) cp_wait<1>();
                else cp_wait<0>();
                __syncthreads();
                const float* w0 = Wsf + (0 * UPB + uj) * WS_F + c4 * 64;
                const float* w1 = Wsf + (1 * UPB + uj) * WS_F + c4 * 64;
                const float* w2 = Wsf + (2 * UPB + uj) * WS_F + c4 * 64;
                const float* w3 = Wsf + (3 * UPB + uj) * WS_F + c4 * 64;
                const float* hcp = hsm + c4 * 1024 + sp;
                #pragma unroll
                for (int kk = 0; kk < 64; kk += 8) {
                    float hr[8];
                    #pragma unroll
                    for (int i = 0; i < 8; i++)
                        hr[i] = hcp[(kk + i) * 16];
                    float4 wa0 = *(const float4*)(w0 + kk);
                    float4 wb0 = *(const float4*)(w0 + kk + 4);
                    float4 wa1 = *(const float4*)(w1 + kk);
                    float4 wb1 = *(const float4*)(w1 + kk + 4);
                    float4 wa2 = *(const float4*)(w2 + kk);
                    float4 wb2 = *(const float4*)(w2 + kk + 4);
                    float4 wa3 = *(const float4*)(w3 + kk);
                    float4 wb3 = *(const float4*)(w3 + kk + 4);
                    a0 = fmaf(hr[0], wa0.x, a0); a0 = fmaf(hr[1], wa0.y, a0);
                    a0 = fmaf(hr[2], wa0.z, a0); a0 = fmaf(hr[3], wa0.w, a0);
                    a0 = fmaf(hr[4], wb0.x, a0); a0 = fmaf(hr[5], wb0.y, a0);
                    a0 = fmaf(hr[6], wb0.z, a0); a0 = fmaf(hr[7], wb0.w, a0);
                    a1 = fmaf(hr[0], wa1.x, a1); a1 = fmaf(hr[1], wa1.y, a1);
                    a1 = fmaf(hr[2], wa1.z, a1); a1 = fmaf(hr[3], wa1.w, a1);
                    a1 = fmaf(hr[4], wb1.x, a1); a1 = fmaf(hr[5], wb1.y, a1);
                    a1 = fmaf(hr[6], wb1.z, a1); a1 = fmaf(hr[7], wb1.w, a1);
                    a2 = fmaf(hr[0], wa2.x, a2); a2 = fmaf(hr[1], wa2.y, a2);
                    a2 = fmaf(hr[2], wa2.z, a2); a2 = fmaf(hr[3], wa2.w, a2);
                    a2 = fmaf(hr[4], wb2.x, a2); a2 = fmaf(hr[5], wb2.y, a2);
                    a2 = fmaf(hr[6], wb2.z, a2); a2 = fmaf(hr[7], wb2.w, a2);
                    a3 = fmaf(hr[0], wa3.x, a3); a3 = fmaf(hr[1], wa3.y, a3);
                    a3 = fmaf(hr[2], wa3.z, a3); a3 = fmaf(hr[3], wa3.w, a3);
                    a3 = fmaf(hr[4], wb3.x, a3); a3 = fmaf(hr[5], wb3.y, a3);
                    a3 = fmaf(hr[6], wb3.z, a3); a3 = fmaf(hr[7], wb3.w, a3);
                }
            }
        }
        float g0 = x0 + a0;
        float g1 = x1 + a1;
        float g2 = x2 + a2;
        float g3 = x3 + a3;
        float ig = 1.f / (1.f + expf(-g0));
        float fg = 1.f / (1.f + expf(-g1));
        float gg = tanhf(g2);
        float og = 1.f / (1.f + expf(-g3));
        float cn = fg * cst + ig * gg;
        float hn = og * tanhf(cn);
        if (t < len_b) { cst = cn; hst = hn; }
        hq_base[((size_t)t * HH + u) * BB + sbs] = hst;

        // publish (release: EVERY thread fences its h store, then sync, then flag)
        __threadfence();
        __syncthreads();
        if (tid == 0) {
            atomicExch((unsigned*)&d_flag[dir][g * BPG + lb],
                       gen0 + (unsigned)s + 1u);
        }
    }
}

// ---------------- 5. projection + mask -> feats[t][b][n] ----------------
__global__ void __launch_bounds__(256) k_proj(const float* __restrict__ proj_w,
                                              const float* __restrict__ proj_b,
                                              const int* __restrict__ lens) {
    __shared__ float hsm[64][64];
    __shared__ float pw[NT][64];
    int t = blockIdx.x;
    int tid = threadIdx.x;
    int b = tid & 63, grp = tid >> 6;
    float acc[13];
    #pragma unroll
    for (int r = 0; r < 13; r++) acc[r] = 0.f;

    for (int kc = 0; kc < 8; kc++) {
        int u512 = kc * 64;
        int dir = u512 >> 8;
        int ubo = u512 & 255;
        const float* hp = &d_hseq[dir][t][ubo][0];
        #pragma unroll
        for (int i = 0; i < 16; i++) {
            int idx = tid + i * 256;
            hsm[idx >> 6][idx & 63] = hp[idx];
        }
        for (int i = tid; i < NT * 64; i += 256) {
            int n = i >> 6, k = i & 63;
            pw[n][k] = proj_w[(size_t)n * (2 * HH) + kc * 64 + k];
        }
        __syncthreads();
        for (int k = 0; k < 64; k++) {
            float hv = hsm[k][b];
            #pragma unroll
            for (int r = 0; r < 13; r++)
                acc[r] += hv * pw[grp * 13 + r][k];
        }
        __syncthreads();
    }
    int msk = (t < lens[b]) ? 1 : 0;
    #pragma unroll
    for (int r = 0; r < 13; r++) {
        int n = grp * 13 + r;
        d_feats[((size_t)t * 64 + b) * NT + n] = (msk ? acc[r] : 0.f) + proj_b[n];
    }
}

// ---------------- 6. CRF: forward Z + viterbi + gold + tags ----------------
__global__ void __launch_bounds__(64) k_crf(const float* __restrict__ transitions,
                                            const int* __restrict__ lens,
                                            const int* __restrict__ labels,
                                            float* __restrict__ out) {
    __shared__ float tr[NT * NT];
    __shared__ float E[NT * NT];
    __shared__ float alpha[2][64], vv[2][64], ea[64], red[64];
    __shared__ unsigned char bps[TT][NT];
    __shared__ int s_best_last;
    int b = blockIdx.x;
    int j = threadIdx.x;

    for (int i = j; i < NT * NT; i += 64) {
        float x = transitions[i];
        tr[i] = x;
        E[i] = expf(x);
    }
    __syncthreads();
    int len = lens[b];

    float aj = -INFINITY;
    if (j < NT) aj = d_feats[(size_t)(0 * 64 + b) * NT + j] + tr[TSTART * NT + j];
    alpha[0][j] = aj;
    vv[0][j] = aj;
    __syncthreads();

    int p = 0;
    for (int t = 1; t < len; t++) {
        int q = p ^ 1;
        float m = alpha[p][0];
        ea[j] = (j < NT) ? expf(alpha[p][j] - m) : 0.f;
        __syncthreads();
        if (j < NT) {
            float ff = d_feats[((size_t)t * 64 + b) * NT + j];
            float s = 0.f;
            #pragma unroll 4
            for (int i = 0; i < NT; i++) s += ea[i] * E[i * NT + j];
            float best = -INFINITY; int bp = 0;
            for (int i = 0; i < NT; i++) {
                float sij = ff + tr[i * NT + j];
                float cnd = vv[p][i] + sij;
                if (cnd > best) { best = cnd; bp = i; }
            }
            alpha[q][j] = m + logf(s) + ff;
            vv[q][j] = best;
            bps[t][j] = (unsigned char)bp;
        }
        __syncthreads();
        p = q;
    }

    float zx = (j < NT) ? alpha[p][j] + tr[j * NT + TSTOP] : -INFINITY;
    red[j] = zx;
    __syncthreads();
    for (int off = 32; off >= 1; off >>= 1) {
        if (j < off) red[j] = fmaxf(red[j], red[j + off]);
        __syncthreads();
    }
    float zm = red[0];
    __syncthreads();
    red[j] = (j < NT) ? expf(zx - zm) : 0.f;
    __syncthreads();
    for (int off = 32; off >= 1; off >>= 1) {
        if (j < off) red[j] += red[j + off];
        __syncthreads();
    }
    float Z = zm + logf(red[0]);
    __syncthreads();

    red[j] = (j < NT) ? vv[p][j] + tr[j * NT + TSTOP] : -INFINITY;
    __syncthreads();
    if (j == 0) {
        float bv = -INFINITY; int bi = 0;
        for (int i = 0; i < NT; i++)
            if (red[i] > bv) { bv = red[i]; bi = i; }
        s_best_last = bi;
    }
    __syncthreads();
    int best_last = s_best_last;
    __syncthreads();

    float gp = 0.f;
    for (int t = j; t < TT; t += 64) {
        if (t < len) {
            int lab = labels[b * TT + t];
            gp += d_feats[((size_t)t * 64 + b) * NT + lab];
            if (t >= 1) gp += tr[labels[b * TT + t - 1] * NT + lab];
        }
    }
    red[j] = gp;
    __syncthreads();
    for (int off = 32; off >= 1; off >>= 1) {
        if (j < off) red[j] += red[j + off];
        __syncthreads();
    }
    if (j == 0) {
        int l0 = labels[b * TT + 0];
        int ll = labels[b * TT + len - 1];
        float gold = red[0] + tr[TSTART * NT + l0] + tr[ll * NT + TSTOP];
        d_lossp[b] = Z - gold;
    }

    if (j == 0) {
        int cur = best_last;
        for (int t = TT - 1; t >= 0; --t) {
            out[1 + b * TT + t] = (t < len) ? (float)cur : 0.f;
            if (t > 0 && t < len) cur = (int)bps[t][cur];
        }
    }
}

// ---------------- 7. loss reduction ----------------
__global__ void k_loss(float* __restrict__ out) {
    __shared__ float red[64];
    int j = threadIdx.x;
    red[j] = d_lossp[j];
    __syncthreads();
    for (int off = 32; off >= 1; off >>= 1) {
        if (j < off) red[j] += red[j + off];
        __syncthreads();
    }
    if (j == 0) out[0] = red[0];
}

// ---------------- launch ----------------
extern "C" void kernel_launch(void* const* d_in, const int* in_sizes, int n_in,
                              void* d_out, int out_size) {
    const int*   batch_word     = (const int*)  d_in[0];
    const int*   batch_features = (const int*)  d_in[1];
    const int*   batch_wordlen  = (const int*)  d_in[2];
    const int*   batch_char     = (const int*)  d_in[3];
    const int*   charrecover    = (const int*)  d_in[5];
    const int*   batch_label    = (const int*)  d_in[7];
    const float* char_emb       = (const float*)d_in[8];
    const float* conv_w         = (const float*)d_in[9];
    const float* conv_b         = (const float*)d_in[10];
    const float* word_emb       = (const float*)d_in[11];
    const float* feat_emb       = (const float*)d_in[12];
    const float* w_ih_f         = (const float*)d_in[13];
    const float* w_hh_f         = (const float*)d_in[14];
    const float* b_f            = (const float*)d_in[15];
    const float* w_ih_b         = (const float*)d_in[16];
    const float* w_hh_b         = (const float*)d_in[17];
    const float* b_b            = (const float*)d_in[18];
    const float* proj_w         = (const float*)d_in[19];
    const float* proj_b         = (const float*)d_in[20];
    const float* transitions    = (const float*)d_in[21];
    float* out = (float*)d_out;
    (void)in_sizes; (void)n_in; (void)out_size;

    const int fused_smem = (64 * WS_F + 4096) * (int)sizeof(float);  // 83,968 B
    static int init_done = 0;
    if (!init_done) {
        cudaFuncSetAttribute(k_fused, cudaFuncAttributeMaxDynamicSharedMemorySize,
                             fused_smem);
        init_done = 1;
    }

    k_zero<<<1, 256>>>();
    k_table<<<(3 * VC * CHN + 255) / 256, 256>>>(conv_w, char_emb);
    k_build_x<<<TT * BB, 128>>>(batch_word, batch_features, batch_char,
                                charrecover, word_emb, feat_emb, conv_b);
    k_fused<<<NLSTM + NG, 256, fused_smem>>>(w_hh_f, w_hh_b, batch_wordlen,
                                             w_ih_f, b_f, w_ih_b, b_b);
    k_proj<<<TT, 256>>>(proj_w, proj_b, batch_wordlen);
    k_crf<<<BB, 64>>>(transitions, batch_wordlen, batch_label, out);
    k_loss<<<1, 64>>>(out);
}